// round 1
// baseline (speedup 1.0000x reference)
#include <cuda_runtime.h>
#include <math.h>

#define NB 4096
#define ND 128
#define INV_T 4.0f          // 1 / 0.25
#define TILE 128
#define PADS 132            // smem row stride in floats (128 + 4 pad, keeps float4 alignment)

// Scratch (no allocations allowed): ~4 MB total
__device__ float g_zi[NB * ND];
__device__ float g_zj[NB * ND];
__device__ float g_rowsum[NB];
__device__ float g_colsum[NB];
__device__ float g_pos[NB];

// ---------------------------------------------------------------------------
// Kernel 1: per-row L2 normalize both embeddings, compute positives,
// and zero the row/col accumulators (fresh every graph replay).
// One block of 128 threads per row.
// ---------------------------------------------------------------------------
__global__ void norm_kernel(const float* __restrict__ emb_i,
                            const float* __restrict__ emb_j) {
    int r = blockIdx.x;
    int t = threadIdx.x;                  // 0..127
    float ei = emb_i[r * ND + t];
    float ej = emb_j[r * ND + t];
    float ssi = ei * ei;
    float ssj = ej * ej;
    float dot = ei * ej;
    #pragma unroll
    for (int o = 16; o > 0; o >>= 1) {
        ssi += __shfl_xor_sync(0xffffffffu, ssi, o);
        ssj += __shfl_xor_sync(0xffffffffu, ssj, o);
        dot += __shfl_xor_sync(0xffffffffu, dot, o);
    }
    __shared__ float s[3][4];
    int w = t >> 5, l = t & 31;
    if (l == 0) { s[0][w] = ssi; s[1][w] = ssj; s[2][w] = dot; }
    __syncthreads();
    ssi = s[0][0] + s[0][1] + s[0][2] + s[0][3];
    ssj = s[1][0] + s[1][1] + s[1][2] + s[1][3];
    dot = s[2][0] + s[2][1] + s[2][2] + s[2][3];
    float inv_i = 1.0f / fmaxf(sqrtf(ssi), 1e-12f);
    float inv_j = 1.0f / fmaxf(sqrtf(ssj), 1e-12f);
    g_zi[r * ND + t] = ei * inv_i;
    g_zj[r * ND + t] = ej * inv_j;
    if (t == 0) {
        g_pos[r]    = dot * inv_i * inv_j;
        g_rowsum[r] = 0.0f;
        g_colsum[r] = 0.0f;
    }
}

// ---------------------------------------------------------------------------
// Kernel 2: fused S = z_i @ z_j^T tile (128x128 per CTA, full K=128),
// exp(S/T) epilogue, partial row/col sums -> global atomics.
// 256 threads, 8x8 outputs per thread.
// ---------------------------------------------------------------------------
__global__ void __launch_bounds__(256) sim_kernel() {
    extern __shared__ float smem[];
    float* As = smem;                 // [128][PADS]
    float* Bs = smem + TILE * PADS;   // [128][PADS]

    int tid = threadIdx.x;
    int tx = tid & 15;                // 0..15 -> col group
    int ty = tid >> 4;                // 0..15 -> row group
    int rowBase = blockIdx.y * TILE;
    int colBase = blockIdx.x * TILE;

    // Load both 128x128 fp32 tiles (64 KB each read) as float4
    const float4* gi = (const float4*)(g_zi + rowBase * ND);
    const float4* gj = (const float4*)(g_zj + colBase * ND);
    #pragma unroll
    for (int i = tid; i < TILE * 32; i += 256) {
        int rr = i >> 5, cc = i & 31;            // row, float4-col
        ((float4*)(As + rr * PADS))[cc] = gi[rr * 32 + cc];
        ((float4*)(Bs + rr * PADS))[cc] = gj[rr * 32 + cc];
    }
    __syncthreads();

    float c[8][8];
    #pragma unroll
    for (int i = 0; i < 8; i++)
        #pragma unroll
        for (int j = 0; j < 8; j++) c[i][j] = 0.0f;

    int ar = ty * 8;
    int bc = tx * 8;

    #pragma unroll 4
    for (int k = 0; k < ND; k += 4) {
        float4 a[8];
        #pragma unroll
        for (int i = 0; i < 8; i++)
            a[i] = *(const float4*)(As + (ar + i) * PADS + k);
        #pragma unroll
        for (int j = 0; j < 8; j++) {
            float4 bv = *(const float4*)(Bs + (bc + j) * PADS + k);
            #pragma unroll
            for (int i = 0; i < 8; i++) {
                c[i][j] = fmaf(a[i].x, bv.x, c[i][j]);
                c[i][j] = fmaf(a[i].y, bv.y, c[i][j]);
                c[i][j] = fmaf(a[i].z, bv.z, c[i][j]);
                c[i][j] = fmaf(a[i].w, bv.w, c[i][j]);
            }
        }
    }

    // Epilogue: exp(S/T), per-thread partial row/col sums
    __shared__ float srow[TILE];
    __shared__ float scol[TILE];
    if (tid < TILE) { srow[tid] = 0.0f; scol[tid] = 0.0f; }
    __syncthreads();

    float rloc[8], cloc[8];
    #pragma unroll
    for (int i = 0; i < 8; i++) { rloc[i] = 0.0f; cloc[i] = 0.0f; }
    #pragma unroll
    for (int i = 0; i < 8; i++) {
        #pragma unroll
        for (int j = 0; j < 8; j++) {
            float e = __expf(c[i][j] * INV_T);
            rloc[i] += e;
            cloc[j] += e;
        }
    }
    #pragma unroll
    for (int i = 0; i < 8; i++) atomicAdd(&srow[ar + i], rloc[i]);
    #pragma unroll
    for (int j = 0; j < 8; j++) atomicAdd(&scol[bc + j], cloc[j]);
    __syncthreads();

    if (tid < TILE) {
        atomicAdd(&g_rowsum[rowBase + tid], srow[tid]);
        atomicAdd(&g_colsum[colBase + tid], scol[tid]);
    }
}

// ---------------------------------------------------------------------------
// Kernel 3: loss = ( sum log(rowsum) + sum log(colsum) - (2/T) sum pos ) / 2B
// ---------------------------------------------------------------------------
__global__ void final_kernel(float* __restrict__ out) {
    int t = threadIdx.x;                  // 256 threads
    double acc = 0.0;
    for (int i = t; i < NB; i += 256) {
        acc += log((double)g_rowsum[i]) + log((double)g_colsum[i])
             - 8.0 * (double)g_pos[i];    // 2/T = 8
    }
    __shared__ double sd[256];
    sd[t] = acc;
    __syncthreads();
    #pragma unroll
    for (int o = 128; o > 0; o >>= 1) {
        if (t < o) sd[t] += sd[t + o];
        __syncthreads();
    }
    if (t == 0) out[0] = (float)(sd[0] / (2.0 * NB));
}

extern "C" void kernel_launch(void* const* d_in, const int* in_sizes, int n_in,
                              void* d_out, int out_size) {
    const float* emb_i = (const float*)d_in[0];
    const float* emb_j = (const float*)d_in[1];
    float* out = (float*)d_out;

    int smem_bytes = 2 * TILE * PADS * sizeof(float);   // 132 KB
    cudaFuncSetAttribute(sim_kernel, cudaFuncAttributeMaxDynamicSharedMemorySize,
                         smem_bytes);

    norm_kernel<<<NB, 128>>>(emb_i, emb_j);
    dim3 grid(NB / TILE, NB / TILE);                    // 32 x 32
    sim_kernel<<<grid, 256, smem_bytes>>>();
    final_kernel<<<1, 256>>>(out);
}

// round 3
// speedup vs baseline: 8.3677x; 8.3677x over previous
#include <cuda_runtime.h>
#include <cuda_bf16.h>
#include <math.h>
#include <cstdint>

#define NB 4096
#define ND 128
#define TILE 128
#define STRIDE 272              // smem bytes per 128-col bf16 row (256 + 16 pad)
#define SM_TILE (128 * STRIDE)  // 34816 B per tile
#define SM_TOTAL (2 * SM_TILE)  // 69632 B

// ---------------- scratch (no allocations allowed) ----------------
__device__ __align__(16) uint2 g_zi_bf[NB * 32];   // bf16 z_i, 4 bf16 per uint2
__device__ __align__(16) uint2 g_zj_bf[NB * 32];   // bf16 z_j
__device__ float g_rowsum[NB];
__device__ float g_colsum[NB];
__device__ float g_pos[NB];

__device__ __forceinline__ uint32_t smem_u32(const void* p) {
    uint32_t a;
    asm("{ .reg .u64 t; cvta.to.shared.u64 t, %1; cvt.u32.u64 %0, t; }" : "=r"(a) : "l"(p));
    return a;
}
__device__ __forceinline__ void ldm_x4(uint32_t& r0, uint32_t& r1, uint32_t& r2,
                                       uint32_t& r3, uint32_t addr) {
    asm volatile("ldmatrix.sync.aligned.m8n8.x4.shared.b16 {%0,%1,%2,%3}, [%4];"
                 : "=r"(r0), "=r"(r1), "=r"(r2), "=r"(r3) : "r"(addr));
}
__device__ __forceinline__ void mma_16816(float& c0, float& c1, float& c2, float& c3,
                                          uint32_t a0, uint32_t a1, uint32_t a2, uint32_t a3,
                                          uint32_t b0, uint32_t b1) {
    asm volatile("mma.sync.aligned.m16n8k16.row.col.f32.bf16.bf16.f32 "
                 "{%0,%1,%2,%3}, {%4,%5,%6,%7}, {%8,%9}, {%0,%1,%2,%3};"
                 : "+f"(c0), "+f"(c1), "+f"(c2), "+f"(c3)
                 : "r"(a0), "r"(a1), "r"(a2), "r"(a3), "r"(b0), "r"(b1));
}

// ---------------------------------------------------------------------------
// Kernel 1: warp-per-row L2 normalize, write bf16 z, fp32 positives, zero sums
// ---------------------------------------------------------------------------
__global__ void __launch_bounds__(256) norm_kernel(const float* __restrict__ emb_i,
                                                   const float* __restrict__ emb_j) {
    int lane = threadIdx.x & 31;
    int row = blockIdx.x * 8 + (threadIdx.x >> 5);
    const float4 a = ((const float4*)emb_i)[row * 32 + lane];
    const float4 b = ((const float4*)emb_j)[row * 32 + lane];
    float ssi = a.x * a.x + a.y * a.y + a.z * a.z + a.w * a.w;
    float ssj = b.x * b.x + b.y * b.y + b.z * b.z + b.w * b.w;
    float dot = a.x * b.x + a.y * b.y + a.z * b.z + a.w * b.w;
#pragma unroll
    for (int o = 16; o > 0; o >>= 1) {
        ssi += __shfl_xor_sync(0xffffffffu, ssi, o);
        ssj += __shfl_xor_sync(0xffffffffu, ssj, o);
        dot += __shfl_xor_sync(0xffffffffu, dot, o);
    }
    float inv_i = 1.0f / fmaxf(sqrtf(ssi), 1e-12f);
    float inv_j = 1.0f / fmaxf(sqrtf(ssj), 1e-12f);

    uint2 oi, oj;
    float zx = a.x * inv_i, zy = a.y * inv_i, zz = a.z * inv_i, zw = a.w * inv_i;
    asm("cvt.rn.bf16x2.f32 %0, %1, %2;" : "=r"(oi.x) : "f"(zy), "f"(zx));
    asm("cvt.rn.bf16x2.f32 %0, %1, %2;" : "=r"(oi.y) : "f"(zw), "f"(zz));
    zx = b.x * inv_j; zy = b.y * inv_j; zz = b.z * inv_j; zw = b.w * inv_j;
    asm("cvt.rn.bf16x2.f32 %0, %1, %2;" : "=r"(oj.x) : "f"(zy), "f"(zx));
    asm("cvt.rn.bf16x2.f32 %0, %1, %2;" : "=r"(oj.y) : "f"(zw), "f"(zz));
    g_zi_bf[row * 32 + lane] = oi;
    g_zj_bf[row * 32 + lane] = oj;
    if (lane == 0) {
        g_pos[row]    = dot * inv_i * inv_j;   // exact fp32 positive
        g_rowsum[row] = 0.0f;
        g_colsum[row] = 0.0f;
    }
}

// ---------------------------------------------------------------------------
// Kernel 2: 128x128 S-tile via mma.sync bf16, fused exp + row/col sums.
// 8 warps: 2 (m) x 4 (n); each warp: 64x32 = 4 m-frags x 4 n-frags of 16x8.
// ---------------------------------------------------------------------------
__global__ void __launch_bounds__(256) sim_kernel() {
    extern __shared__ char smem[];
    __shared__ float srow[TILE];
    __shared__ float scol[TILE];

    uint32_t sA = smem_u32(smem);
    uint32_t sB = sA + SM_TILE;
    int tid = threadIdx.x;
    int wid = tid >> 5;
    int l = tid & 31;
    int rowBase = blockIdx.y * TILE;
    int colBase = blockIdx.x * TILE;
    int m_base = (wid & 1) * 64;
    int n_base = (wid >> 1) * 32;

    if (tid < TILE) { srow[tid] = 0.0f; scol[tid] = 0.0f; }

    // --- global -> smem (16B chunks); row stride 272 B kills ldmatrix conflicts
    const uint4* gi = (const uint4*)(g_zi_bf + rowBase * 32);   // 16 uint4/row
    const uint4* gj = (const uint4*)(g_zj_bf + colBase * 32);
#pragma unroll
    for (int it = 0; it < 8; it++) {
        int i = it * 256 + tid;              // [0, 2048)
        int row = i >> 4, chunk = i & 15;
        uint32_t off = (uint32_t)row * STRIDE + chunk * 16;
        *(uint4*)(smem + off) = gi[i];
        *(uint4*)(smem + SM_TILE + off) = gj[i];
    }
    __syncthreads();

    // --- per-lane ldmatrix base addresses ---
    // x4 lane mapping: matrix j = l>>3 (rows l&7), matrices:
    // (r0-7,kLo),(r8-15,kLo),(r0-7,kHi),(r8-15,kHi) -> frag regs in order.
    uint32_t lrow = (uint32_t)(((l >> 3) & 1) * 8 + (l & 7));
    uint32_t lcolb = (uint32_t)((l >> 4) * 16);                 // 8 cols * 2B
    uint32_t a_base = sA + (m_base + lrow) * STRIDE + lcolb;
    uint32_t b_base = sB + (n_base + lrow) * STRIDE + lcolb;

    float c[4][4][4];
#pragma unroll
    for (int mf = 0; mf < 4; mf++)
#pragma unroll
        for (int nf = 0; nf < 4; nf++)
#pragma unroll
            for (int e = 0; e < 4; e++) c[mf][nf][e] = 0.0f;

#pragma unroll
    for (int ks = 0; ks < 8; ks++) {
        uint32_t koff = (uint32_t)ks * 32;                      // 16 bf16 = 32 B
        uint32_t a0[4], a1[4], a2[4], a3[4];
#pragma unroll
        for (int mf = 0; mf < 4; mf++)
            ldm_x4(a0[mf], a1[mf], a2[mf], a3[mf],
                   a_base + (uint32_t)mf * 16 * STRIDE + koff);
        uint32_t bl0[2], bl1[2], bl2[2], bl3[2];
#pragma unroll
        for (int nh = 0; nh < 2; nh++)
            ldm_x4(bl0[nh], bl1[nh], bl2[nh], bl3[nh],
                   b_base + (uint32_t)nh * 16 * STRIDE + koff);
#pragma unroll
        for (int mf = 0; mf < 4; mf++) {
#pragma unroll
            for (int nh = 0; nh < 2; nh++) {
                // n-frag even (n0-7 of this 16): regs {m0, m2}; odd: {m1, m3}
                mma_16816(c[mf][nh * 2][0], c[mf][nh * 2][1],
                          c[mf][nh * 2][2], c[mf][nh * 2][3],
                          a0[mf], a1[mf], a2[mf], a3[mf], bl0[nh], bl2[nh]);
                mma_16816(c[mf][nh * 2 + 1][0], c[mf][nh * 2 + 1][1],
                          c[mf][nh * 2 + 1][2], c[mf][nh * 2 + 1][3],
                          a0[mf], a1[mf], a2[mf], a3[mf], bl1[nh], bl3[nh]);
            }
        }
    }

    // --- epilogue: exp + in-register row/col partial sums ---
    // frag elem map: c0:(r, cc) c1:(r, cc+1) c2:(r+8, cc) c3:(r+8, cc+1)
    // with r = l/4, cc = 2*(l%4)
    float rlo[4], rhi[4], ceven[4], codd[4];
#pragma unroll
    for (int i = 0; i < 4; i++) { ceven[i] = 0.0f; codd[i] = 0.0f; }
#pragma unroll
    for (int mf = 0; mf < 4; mf++) { rlo[mf] = 0.0f; rhi[mf] = 0.0f; }
#pragma unroll
    for (int mf = 0; mf < 4; mf++) {
#pragma unroll
        for (int nf = 0; nf < 4; nf++) {
            float e0 = __expf(c[mf][nf][0] * 4.0f);   // 1/T = 4
            float e1 = __expf(c[mf][nf][1] * 4.0f);
            float e2 = __expf(c[mf][nf][2] * 4.0f);
            float e3 = __expf(c[mf][nf][3] * 4.0f);
            rlo[mf] += e0 + e1;
            rhi[mf] += e2 + e3;
            ceven[nf] += e0 + e2;
            codd[nf]  += e1 + e3;
        }
    }
    // row sums: reduce over col-pair lanes (l%4 varies) -> full 32-col partial
#pragma unroll
    for (int mf = 0; mf < 4; mf++) {
#pragma unroll
        for (int o = 1; o <= 2; o <<= 1) {
            rlo[mf] += __shfl_xor_sync(0xffffffffu, rlo[mf], o);
            rhi[mf] += __shfl_xor_sync(0xffffffffu, rhi[mf], o);
        }
        if ((l & 3) == 0) {
            int r = m_base + mf * 16 + (l >> 2);
            atomicAdd(&srow[r], rlo[mf]);
            atomicAdd(&srow[r + 8], rhi[mf]);
        }
    }
    // col sums: reduce over row lanes (l/4 varies) -> full 64-row partial
#pragma unroll
    for (int nf = 0; nf < 4; nf++) {
#pragma unroll
        for (int o = 4; o <= 16; o <<= 1) {
            ceven[nf] += __shfl_xor_sync(0xffffffffu, ceven[nf], o);
            codd[nf]  += __shfl_xor_sync(0xffffffffu, codd[nf], o);
        }
        if (l < 4) {
            int cc = n_base + nf * 8 + 2 * l;
            atomicAdd(&scol[cc], ceven[nf]);
            atomicAdd(&scol[cc + 1], codd[nf]);
        }
    }
    __syncthreads();

    if (tid < TILE) {
        atomicAdd(&g_rowsum[rowBase + tid], srow[tid]);
        atomicAdd(&g_colsum[colBase + tid], scol[tid]);
    }
}

// ---------------------------------------------------------------------------
// Kernel 3: loss = ( sum log(rowsum)+log(colsum) - (2/T) sum pos ) / 2B
// ---------------------------------------------------------------------------
__global__ void final_kernel(float* __restrict__ out) {
    int t = threadIdx.x;
    double acc = 0.0;
    for (int i = t; i < NB; i += 256) {
        acc += (double)__logf(g_rowsum[i]) + (double)__logf(g_colsum[i])
             - 8.0 * (double)g_pos[i];                        // 2/T = 8
    }
    __shared__ double sd[256];
    sd[t] = acc;
    __syncthreads();
#pragma unroll
    for (int o = 128; o > 0; o >>= 1) {
        if (t < o) sd[t] += sd[t + o];
        __syncthreads();
    }
    if (t == 0) out[0] = (float)(sd[0] / (2.0 * NB));
}

extern "C" void kernel_launch(void* const* d_in, const int* in_sizes, int n_in,
                              void* d_out, int out_size) {
    const float* emb_i = (const float*)d_in[0];
    const float* emb_j = (const float*)d_in[1];
    float* out = (float*)d_out;

    cudaFuncSetAttribute(sim_kernel, cudaFuncAttributeMaxDynamicSharedMemorySize, SM_TOTAL);

    norm_kernel<<<NB / 8, 256>>>(emb_i, emb_j);
    dim3 grid(NB / TILE, NB / TILE);       // 32 x 32
    sim_kernel<<<grid, 256, SM_TOTAL>>>();
    final_kernel<<<1, 256>>>(out);
}